// round 1
// baseline (speedup 1.0000x reference)
#include <cuda_runtime.h>
#include <cstdint>

#define NVOX   (64*128*128)        // 1048576 voxels per image
#define NB     2
#define NC     32
#define PCAP   2048
#define NCAP   12288
#define COLCAP (PCAP+NCAP)         // 14336
#define CHUNK  256
#define CCH    56                  // 56*256 = 14336 column chunks
#define TILE   128
#define NBLK   512                 // compaction blocks per image
#define VPB    2048                // voxels per compaction block

typedef unsigned long long ull;

// ---------------- device scratch (no allocations allowed) ----------------
__device__ __align__(16) unsigned char g_fg [NB*NVOX];
__device__ __align__(16) unsigned char g_d0 [NB*NVOX];
__device__ __align__(16) unsigned char g_d1 [NB*NVOX];
__device__ __align__(16) unsigned char g_rim[NB*NVOX];
__device__ int    g_blk[NB][NBLK][2];
__device__ int    g_off[NB][NBLK][2];
__device__ int    g_cnt[NB][2];
__device__ int    g_posIdx[NB][PCAP];
__device__ int    g_negIdx[NB][NCAP];
__device__ float4 g_posF[NB][PCAP][8];    // 32 floats per row, fp32, L2-normalized
__device__ float4 g_negF[NB][NCAP][8];
__device__ float  g_part[NB][PCAP][CCH][2];
__device__ float  g_imgLoss[NB];
__device__ int    g_imgValid[NB];

// ---------------- stage 1: fg mask ----------------
__global__ void k_fg(const int* __restrict__ lab) {
    int t = blockIdx.x * 256 + threadIdx.x;
    if (t < NB*NVOX) g_fg[t] = (lab[t] > 0) ? 1 : 0;
}

// ---------------- stage 2: separable binary dilation (11^3, SAME, pad=0) ----
// masks are 0/1 -> max == OR
__global__ void k_dilw() {   // along W (stride 1)
    int t = blockIdx.x * 256 + threadIdx.x;
    if (t >= NB*NVOX/4) return;
    int w4  = t & 31;
    int row = t >> 5;                       // (img*64+d)*128 + h
    const unsigned char* src = g_fg + row*128;
    int w0 = w4 * 4;
    unsigned char m0=0,m1=0,m2=0,m3=0;
    #pragma unroll
    for (int k = -5; k <= 8; ++k) {
        int w = w0 + k;
        unsigned char v = ((unsigned)w < 128u) ? src[w] : (unsigned char)0;
        if (k >= -5 && k <= 5) m0 |= v;
        if (k >= -4 && k <= 6) m1 |= v;
        if (k >= -3 && k <= 7) m2 |= v;
        if (k >= -2 && k <= 8) m3 |= v;
    }
    unsigned out = (unsigned)m0 | ((unsigned)m1<<8) | ((unsigned)m2<<16) | ((unsigned)m3<<24);
    *reinterpret_cast<unsigned*>(g_d0 + row*128 + w0) = out;
}
__global__ void k_dilh() {   // along H (stride 128)
    int t = blockIdx.x * 256 + threadIdx.x;
    if (t >= NB*NVOX/4) return;
    int w  = t & 127;
    int h4 = (t >> 7) & 31;
    int pl = t >> 12;                        // img*64+d in [0,128)
    const unsigned char* src = g_d0 + pl*16384 + w;
    int h0 = h4 * 4;
    unsigned char m0=0,m1=0,m2=0,m3=0;
    #pragma unroll
    for (int k = -5; k <= 8; ++k) {
        int h = h0 + k;
        unsigned char v = ((unsigned)h < 128u) ? src[h*128] : (unsigned char)0;
        if (k >= -5 && k <= 5) m0 |= v;
        if (k >= -4 && k <= 6) m1 |= v;
        if (k >= -3 && k <= 7) m2 |= v;
        if (k >= -2 && k <= 8) m3 |= v;
    }
    unsigned char* dst = g_d1 + pl*16384 + w;
    dst[(h0+0)*128]=m0; dst[(h0+1)*128]=m1; dst[(h0+2)*128]=m2; dst[(h0+3)*128]=m3;
}
__global__ void k_dild() {   // along D (stride 16384) + rim = dil & !fg
    int t = blockIdx.x * 256 + threadIdx.x;
    if (t >= NB*NVOX/4) return;
    int w   = t & 127;
    int h   = (t >> 7) & 127;
    int d4  = (t >> 14) & 15;
    int img = t >> 18;
    size_t base = (size_t)img*NVOX + h*128 + w;
    int d0 = d4 * 4;
    unsigned char m0=0,m1=0,m2=0,m3=0;
    #pragma unroll
    for (int k = -5; k <= 8; ++k) {
        int d = d0 + k;
        unsigned char v = ((unsigned)d < 64u) ? g_d1[base + (size_t)d*16384] : (unsigned char)0;
        if (k >= -5 && k <= 5) m0 |= v;
        if (k >= -4 && k <= 6) m1 |= v;
        if (k >= -3 && k <= 7) m2 |= v;
        if (k >= -2 && k <= 8) m3 |= v;
    }
    g_rim[base + (size_t)(d0+0)*16384] = m0 & (g_fg[base + (size_t)(d0+0)*16384] ^ 1);
    g_rim[base + (size_t)(d0+1)*16384] = m1 & (g_fg[base + (size_t)(d0+1)*16384] ^ 1);
    g_rim[base + (size_t)(d0+2)*16384] = m2 & (g_fg[base + (size_t)(d0+2)*16384] ^ 1);
    g_rim[base + (size_t)(d0+3)*16384] = m3 & (g_fg[base + (size_t)(d0+3)*16384] ^ 1);
}

// ---------------- stage 3: deterministic ordered compaction ----------------
__global__ void k_count() {      // grid (NBLK, NB), 256 threads, 8 voxels each
    int img = blockIdx.y;
    int tid = threadIdx.x;
    size_t s = (size_t)blockIdx.x * VPB + tid * 8;
    ull pf = *reinterpret_cast<const ull*>(g_fg  + (size_t)img*NVOX + s);
    ull pr = *reinterpret_cast<const ull*>(g_rim + (size_t)img*NVOX + s);
    int cp = __popcll(pf);       // bytes are exactly 0/1
    int cr = __popcll(pr);
    #pragma unroll
    for (int o = 16; o; o >>= 1) {
        cp += __shfl_down_sync(0xffffffffu, cp, o);
        cr += __shfl_down_sync(0xffffffffu, cr, o);
    }
    __shared__ int sp[8], sr[8];
    if ((tid & 31) == 0) { sp[tid>>5] = cp; sr[tid>>5] = cr; }
    __syncthreads();
    if (tid == 0) {
        int a=0, b=0;
        #pragma unroll
        for (int i=0;i<8;i++){ a += sp[i]; b += sr[i]; }
        g_blk[img][blockIdx.x][0] = a;
        g_blk[img][blockIdx.x][1] = b;
    }
}
__global__ void k_scan() {       // grid NB, NBLK threads: exclusive scan
    int img = blockIdx.x;
    int tid = threadIdx.x;
    __shared__ int sp[NBLK], sn[NBLK];
    int p = g_blk[img][tid][0];
    int r = g_blk[img][tid][1];
    sp[tid] = p; sn[tid] = r;
    __syncthreads();
    for (int off = 1; off < NBLK; off <<= 1) {
        int vp = 0, vn = 0;
        if (tid >= off) { vp = sp[tid-off]; vn = sn[tid-off]; }
        __syncthreads();
        sp[tid] += vp; sn[tid] += vn;
        __syncthreads();
    }
    g_off[img][tid][0] = sp[tid] - p;      // exclusive
    g_off[img][tid][1] = sn[tid] - r;
    if (tid == NBLK-1) { g_cnt[img][0] = sp[tid]; g_cnt[img][1] = sn[tid]; }
}
__global__ void k_emit() {       // grid (NBLK, NB), 256 threads
    int img = blockIdx.y;
    int tid = threadIdx.x;
    int lane = tid & 31, wid = tid >> 5;
    size_t s0 = (size_t)blockIdx.x * VPB + tid * 8;
    ull pf = *reinterpret_cast<const ull*>(g_fg  + (size_t)img*NVOX + s0);
    ull pr = *reinterpret_cast<const ull*>(g_rim + (size_t)img*NVOX + s0);
    int cp = __popcll(pf), cr = __popcll(pr);
    int ip = cp, ir = cr;                   // warp inclusive scan
    #pragma unroll
    for (int o = 1; o < 32; o <<= 1) {
        int tp = __shfl_up_sync(0xffffffffu, ip, o);
        int tr = __shfl_up_sync(0xffffffffu, ir, o);
        if (lane >= o) { ip += tp; ir += tr; }
    }
    __shared__ int wp[8], wr[8], bp[8], br[8];
    if (lane == 31) { wp[wid] = ip; wr[wid] = ir; }
    __syncthreads();
    if (tid == 0) {
        int ap=0, ar=0;
        #pragma unroll
        for (int i=0;i<8;i++){ bp[i]=ap; br[i]=ar; ap+=wp[i]; ar+=wr[i]; }
    }
    __syncthreads();
    int op  = g_off[img][blockIdx.x][0] + bp[wid] + (ip - cp);
    int orr = g_off[img][blockIdx.x][1] + br[wid] + (ir - cr);
    #pragma unroll
    for (int i = 0; i < 8; ++i) {
        if ((pf >> (8*i)) & 1ull) { if (op  < PCAP) g_posIdx[img][op]  = (int)(s0 + i); op++; }
        if ((pr >> (8*i)) & 1ull) { if (orr < NCAP) g_negIdx[img][orr] = (int)(s0 + i); orr++; }
    }
}

// ---------------- stage 4: gather + L2-normalize selected rows --------------
__global__ void k_gather(const float* __restrict__ feats) {
    int t = blockIdx.x * 256 + threadIdx.x;
    int img = t / COLCAP;
    if (img >= NB) return;
    int s = t - img * COLCAP;
    int posCnt = min(g_cnt[img][0], PCAP);
    int negCnt = min(g_cnt[img][1], NCAP);
    int n; float4* dst;
    if (s < PCAP) {
        if (s >= posCnt) return;
        n = g_posIdx[img][s]; dst = g_posF[img][s];
    } else {
        int j = s - PCAP;
        if (j >= negCnt) return;
        n = g_negIdx[img][j]; dst = g_negF[img][j];
    }
    const float* f = feats + (size_t)img * NC * NVOX + n;
    float v[NC]; float ss = 0.f;
    #pragma unroll
    for (int c = 0; c < NC; ++c) { v[c] = __ldg(f + (size_t)c * NVOX); ss += v[c]*v[c]; }
    float sc = 1.0f / fmaxf(sqrtf(ss), 1e-12f);
    #pragma unroll
    for (int u = 0; u < 8; ++u)
        dst[u] = make_float4(v[4*u]*sc, v[4*u+1]*sc, v[4*u+2]*sc, v[4*u+3]*sc);
}

// ---------------- stage 5: main contraction + single-pass softmax sums ------
// Each block: 256 anchors (2/thread) x one 256-column chunk; tiles of 128 cols
// in SMEM; dot via packed fp32 FFMA2 (fma.rn.f32x2). exp is unshifted: logits
// bounded by 1/tau = 10 so no overflow; EPS effect < 1e-7 relative.
__global__ void __launch_bounds__(128) k_main() {
    int img = blockIdx.z;
    int posCnt = min(g_cnt[img][0], PCAP);
    int negCnt = min(g_cnt[img][1], NCAP);
    int nCol = posCnt + negCnt;
    int aBase = blockIdx.x * 256;
    int cBase = blockIdx.y * CHUNK;
    if (aBase >= posCnt || cBase >= nCol) return;
    int tid = threadIdx.x;
    int a0 = aBase + tid, a1 = a0 + 128;     // both < PCAP by construction

    ulonglong2 A0[8], A1[8];
    {
        const ulonglong2* p0 = reinterpret_cast<const ulonglong2*>(&g_posF[img][a0][0]);
        const ulonglong2* p1 = reinterpret_cast<const ulonglong2*>(&g_posF[img][a1][0]);
        #pragma unroll
        for (int u = 0; u < 8; ++u) { A0[u] = p0[u]; A1[u] = p1[u]; }
    }
    __shared__ float4 s_tile[TILE * 8];      // [col][8 x float4] = 16 KB
    float num0 = 0.f, neg0 = 0.f, num1 = 0.f, neg1 = 0.f;
    int cEnd = min(cBase + CHUNK, nCol);
    for (int tb = cBase; tb < cEnd; tb += TILE) {
        int tc = min(TILE, cEnd - tb);
        if (tid < tc) {
            int g = tb + tid;
            const float4* src = (g < posCnt) ? &g_posF[img][g][0]
                                             : &g_negF[img][g - posCnt][0];
            #pragma unroll
            for (int u = 0; u < 8; ++u) s_tile[tid*8 + u] = src[u];
        }
        __syncthreads();
        #pragma unroll 4
        for (int j = 0; j < tc; ++j) {
            const ulonglong2* cv = reinterpret_cast<const ulonglong2*>(&s_tile[j*8]);
            ull s00 = 0ull, s01 = 0ull, s10 = 0ull, s11 = 0ull;
            #pragma unroll
            for (int u = 0; u < 8; ++u) {
                ulonglong2 v = cv[u];
                asm("fma.rn.f32x2 %0, %1, %2, %0;" : "+l"(s00) : "l"(A0[u].x), "l"(v.x));
                asm("fma.rn.f32x2 %0, %1, %2, %0;" : "+l"(s01) : "l"(A0[u].y), "l"(v.y));
                asm("fma.rn.f32x2 %0, %1, %2, %0;" : "+l"(s10) : "l"(A1[u].x), "l"(v.x));
                asm("fma.rn.f32x2 %0, %1, %2, %0;" : "+l"(s11) : "l"(A1[u].y), "l"(v.y));
            }
            ull t0, t1;
            asm("add.rn.f32x2 %0, %1, %2;" : "=l"(t0) : "l"(s00), "l"(s01));
            asm("add.rn.f32x2 %0, %1, %2;" : "=l"(t1) : "l"(s10), "l"(s11));
            float d0 = __uint_as_float((unsigned)t0) + __uint_as_float((unsigned)(t0 >> 32));
            float d1 = __uint_as_float((unsigned)t1) + __uint_as_float((unsigned)(t1 >> 32));
            float e0 = __expf(d0 * 10.0f);   // 1/TAU
            float e1 = __expf(d1 * 10.0f);
            int jg = tb + j;
            if (jg < posCnt) {
                if (jg != a0) num0 += e0;
                if (jg != a1) num1 += e1;
            } else { neg0 += e0; neg1 += e1; }
        }
        __syncthreads();
    }
    if (a0 < posCnt) { g_part[img][a0][blockIdx.y][0] = num0; g_part[img][a0][blockIdx.y][1] = neg0; }
    if (a1 < posCnt) { g_part[img][a1][blockIdx.y][0] = num1; g_part[img][a1][blockIdx.y][1] = neg1; }
}

// ---------------- stage 6: deterministic per-image reduction ----------------
__global__ void k_reduce() {     // grid NB, 256 threads
    int img = blockIdx.x;
    int tid = threadIdx.x;
    int posCnt = min(g_cnt[img][0], PCAP);
    int negCnt = min(g_cnt[img][1], NCAP);
    float sum = 0.f, cnt = 0.f;
    for (int a = tid; a < posCnt; a += 256) {
        float num = 0.f, neg = 0.f;
        #pragma unroll 8
        for (int c = 0; c < CCH; ++c) {
            num += g_part[img][a][c][0];
            neg += g_part[img][a][c][1];
        }
        if (num > 0.f) { sum += log1pf(neg / num); cnt += 1.f; }  // -log(num/(num+neg))
    }
    __shared__ float ss[256], sc[256];
    ss[tid] = sum; sc[tid] = cnt;
    __syncthreads();
    for (int o = 128; o > 0; o >>= 1) {
        if (tid < o) { ss[tid] += ss[tid + o]; sc[tid] += sc[tid + o]; }
        __syncthreads();
    }
    if (tid == 0) {
        g_imgLoss[img]  = ss[0] / fmaxf(sc[0], 1.f);
        g_imgValid[img] = (posCnt >= 2 && negCnt > 0 && sc[0] > 0.f) ? 1 : 0;
    }
}
__global__ void k_final(float* out) {
    float v0 = g_imgValid[0] ? 1.f : 0.f;
    float v1 = g_imgValid[1] ? 1.f : 0.f;
    float s = g_imgLoss[0]*v0 + g_imgLoss[1]*v1;
    float tot = s / fmaxf(v0 + v1, 1.f);
    out[0] = (v0 + v1 > 0.f) ? tot : 0.f;
}

// ---------------- launch ----------------
extern "C" void kernel_launch(void* const* d_in, const int* in_sizes, int n_in,
                              void* d_out, int out_size) {
    const float* feats = (const float*)d_in[0];
    const int*   lab   = (const int*)d_in[1];
    (void)in_sizes; (void)n_in; (void)out_size;

    k_fg  <<<(NB*NVOX + 255)/256, 256>>>(lab);
    k_dilw<<<(NB*NVOX/4 + 255)/256, 256>>>();
    k_dilh<<<(NB*NVOX/4 + 255)/256, 256>>>();
    k_dild<<<(NB*NVOX/4 + 255)/256, 256>>>();
    k_count<<<dim3(NBLK, NB), 256>>>();
    k_scan <<<NB, NBLK>>>();
    k_emit <<<dim3(NBLK, NB), 256>>>();
    k_gather<<<(NB*COLCAP + 255)/256, 256>>>(feats);
    k_main <<<dim3(PCAP/256, CCH, NB), 128>>>();
    k_reduce<<<NB, 256>>>();
    k_final<<<1, 1>>>((float*)d_out);
}

// round 2
// speedup vs baseline: 2.7584x; 2.7584x over previous
#include <cuda_runtime.h>
#include <cstdint>

#define NVOX   (64*128*128)        // 1048576 voxels per image
#define NB     2
#define NC     32
#define PCAP   2048
#define NCAP   12288
#define COLCAP (PCAP+NCAP)         // 14336
#define CHUNK  256
#define CCH    56                  // 56*256 = 14336 column chunks
#define NROWS  (NB*64*128)         // 16384 (img,d,h) rows of 128 voxels

typedef unsigned long long ull;

// ---------------- device scratch (no allocations allowed) ----------------
__device__ unsigned g_bf[NROWS*4];     // fg bits,   1 bit/voxel, 4 words/row
__device__ unsigned g_bw[NROWS*4];     // W-dilated
__device__ unsigned g_bh[NROWS*4];     // W+H-dilated
__device__ int    g_cnt[NB][2];
__device__ int    g_done;
__device__ int    g_posIdx[NB][PCAP];
__device__ int    g_negIdx[NB][NCAP];
__device__ float4 g_posF[NB][PCAP][8];    // 32 floats per row, L2-normalized
__device__ float4 g_negF[NB][NCAP][8];
__device__ float  g_part[NB][PCAP][CCH][2];
__device__ float  g_imgLoss[NB];
__device__ int    g_imgValid[NB];

// idx helper: (plane, h, word) -> word index; plane = img*64 + d
__device__ __forceinline__ int bidx(int pl, int h, int w) { return pl*512 + h*4 + w; }

// ---------------- stage 1: fg bitmask + W-dilation (fused) ------------------
// 8 warps/block, 1 warp per (img,d,h) row of 128 voxels.
__global__ void k_pack(const int* __restrict__ lab) {
    int warp = threadIdx.x >> 5, lane = threadIdx.x & 31;
    int row  = blockIdx.x * 8 + warp;            // [0, NROWS)
    __shared__ unsigned srow[8][4];
    if (lane < 4) srow[warp][lane] = 0;
    __syncwarp();
    int4 l = *reinterpret_cast<const int4*>(lab + (size_t)row*128 + lane*4);
    unsigned nib = (unsigned)(l.x > 0) | ((unsigned)(l.y > 0) << 1)
                 | ((unsigned)(l.z > 0) << 2) | ((unsigned)(l.w > 0) << 3);
    if (nib) atomicOr(&srow[warp][lane >> 3], nib << ((lane & 7) * 4));
    __syncwarp();
    if (lane < 4) {
        unsigned f  = srow[warp][lane];
        unsigned fl = (lane > 0) ? srow[warp][lane-1] : 0u;
        unsigned fr = (lane < 3) ? srow[warp][lane+1] : 0u;
        unsigned dil = f;
        #pragma unroll
        for (int k = 1; k <= 5; ++k) {
            dil |= __funnelshift_r(f, fr, k);    // 128-bit >> k, this word
            dil |= __funnelshift_l(fl, f, k);    // 128-bit << k, this word
        }
        g_bf[row*4 + lane] = f;
        g_bw[row*4 + lane] = dil;
    }
    if (blockIdx.x == 0 && threadIdx.x == 0) {
        g_cnt[0][0] = g_cnt[0][1] = g_cnt[1][0] = g_cnt[1][1] = 0;
        g_done = 0;
    }
}

// ---------------- stage 2: H-dilation on bit-words --------------------------
__global__ void k_dilh() {
    int t = blockIdx.x * 256 + threadIdx.x;      // [0, NROWS*4) = 65536
    int w  = t & 3;
    int h  = (t >> 2) & 127;
    int pl = t >> 9;
    unsigned acc = 0;
    #pragma unroll
    for (int k = -5; k <= 5; ++k) {
        int hh = h + k;
        if ((unsigned)hh < 128u) acc |= g_bw[bidx(pl, hh, w)];
    }
    g_bh[bidx(pl, h, w)] = acc;
}

// ---------------- stage 3: D-dilation + rim + atomic emit -------------------
__global__ void k_demit() {
    int t = blockIdx.x * 256 + threadIdx.x;      // 65536
    int w   = t & 3;
    int h   = (t >> 2) & 127;
    int pl  = t >> 9;
    int img = pl >> 6, d = pl & 63;
    unsigned acc = 0;
    #pragma unroll
    for (int k = -5; k <= 5; ++k) {
        int dd = d + k;
        if ((unsigned)dd < 64u) acc |= g_bh[bidx(img*64 + dd, h, w)];
    }
    unsigned fgw = g_bf[bidx(pl, h, w)];
    unsigned rim = acc & ~fgw;
    int vbase = d*16384 + h*128 + w*32;
    if (fgw) {
        int c = __popc(fgw);
        int base = atomicAdd(&g_cnt[img][0], c);
        unsigned m = fgw;
        while (m) {
            int b = __ffs(m) - 1; m &= m - 1;
            if (base < PCAP) g_posIdx[img][base] = vbase + b;
            base++;
        }
    }
    if (rim) {
        int c = __popc(rim);
        int base = atomicAdd(&g_cnt[img][1], c);
        unsigned m = rim;
        while (m) {
            int b = __ffs(m) - 1; m &= m - 1;
            if (base < NCAP) g_negIdx[img][base] = vbase + b;
            base++;
        }
    }
}

// ---------------- stage 4: gather + L2-normalize selected rows --------------
__global__ void k_gather(const float* __restrict__ feats) {
    int t = blockIdx.x * 256 + threadIdx.x;
    int img = t / COLCAP;
    if (img >= NB) return;
    int s = t - img * COLCAP;
    int posCnt = min(g_cnt[img][0], PCAP);
    int negCnt = min(g_cnt[img][1], NCAP);
    int n; float4* dst;
    if (s < PCAP) {
        if (s >= posCnt) return;
        n = g_posIdx[img][s]; dst = g_posF[img][s];
    } else {
        int j = s - PCAP;
        if (j >= negCnt) return;
        n = g_negIdx[img][j]; dst = g_negF[img][j];
    }
    const float* f = feats + (size_t)img * NC * NVOX + n;
    float v[NC]; float ss = 0.f;
    #pragma unroll
    for (int c = 0; c < NC; ++c) { v[c] = __ldg(f + (size_t)c * NVOX); ss += v[c]*v[c]; }
    float sc = 1.0f / fmaxf(sqrtf(ss), 1e-12f);
    #pragma unroll
    for (int u = 0; u < 8; ++u)
        dst[u] = make_float4(v[4*u]*sc, v[4*u+1]*sc, v[4*u+2]*sc, v[4*u+3]*sc);
}

// ---------------- stage 5: main contraction + single-pass softmax sums ------
// 256 anchors/block (2 per thread) x one 256-column chunk staged in SMEM.
// Dot via packed fp32 FFMA2 (fma.rn.f32x2); exp unshifted (|logit| <= 10).
// Register budget kept < ~140 (A: 64, accum: 16, staging for unroll-2) to
// avoid the spill suspected in round 1's unroll-4 version.
__global__ void __launch_bounds__(128, 3) k_main() {
    int img = blockIdx.z;
    int posCnt = min(g_cnt[img][0], PCAP);
    int negCnt = min(g_cnt[img][1], NCAP);
    int nCol = posCnt + negCnt;
    int aBase = blockIdx.x * 256;
    int cBase = blockIdx.y * CHUNK;
    if (aBase >= posCnt || cBase >= nCol) return;
    int tid = threadIdx.x;
    int a0 = aBase + tid, a1 = a0 + 128;

    ulonglong2 A0[8], A1[8];
    {
        const ulonglong2* p0 = reinterpret_cast<const ulonglong2*>(&g_posF[img][a0][0]);
        const ulonglong2* p1 = reinterpret_cast<const ulonglong2*>(&g_posF[img][a1][0]);
        #pragma unroll
        for (int u = 0; u < 8; ++u) { A0[u] = p0[u]; A1[u] = p1[u]; }
    }
    __shared__ float4 s_tile[CHUNK * 8];         // 32 KB
    int tc = min(CHUNK, nCol - cBase);
    for (int g0 = tid; g0 < tc; g0 += 128) {
        int g = cBase + g0;
        const float4* src = (g < posCnt) ? &g_posF[img][g][0]
                                         : &g_negF[img][g - posCnt][0];
        #pragma unroll
        for (int u = 0; u < 8; ++u) s_tile[g0*8 + u] = src[u];
    }
    __syncthreads();

    float num0 = 0.f, neg0 = 0.f, num1 = 0.f, neg1 = 0.f;
    #pragma unroll 2
    for (int j = 0; j < tc; ++j) {
        const ulonglong2* cv = reinterpret_cast<const ulonglong2*>(&s_tile[j*8]);
        ull s00 = 0ull, s01 = 0ull, s10 = 0ull, s11 = 0ull;
        #pragma unroll
        for (int u = 0; u < 8; ++u) {
            ulonglong2 v = cv[u];
            asm("fma.rn.f32x2 %0, %1, %2, %0;" : "+l"(s00) : "l"(A0[u].x), "l"(v.x));
            asm("fma.rn.f32x2 %0, %1, %2, %0;" : "+l"(s01) : "l"(A0[u].y), "l"(v.y));
            asm("fma.rn.f32x2 %0, %1, %2, %0;" : "+l"(s10) : "l"(A1[u].x), "l"(v.x));
            asm("fma.rn.f32x2 %0, %1, %2, %0;" : "+l"(s11) : "l"(A1[u].y), "l"(v.y));
        }
        ull t0, t1;
        asm("add.rn.f32x2 %0, %1, %2;" : "=l"(t0) : "l"(s00), "l"(s01));
        asm("add.rn.f32x2 %0, %1, %2;" : "=l"(t1) : "l"(s10), "l"(s11));
        float d0 = __uint_as_float((unsigned)t0) + __uint_as_float((unsigned)(t0 >> 32));
        float d1 = __uint_as_float((unsigned)t1) + __uint_as_float((unsigned)(t1 >> 32));
        float e0 = __expf(d0 * 10.0f);           // 1/TAU
        float e1 = __expf(d1 * 10.0f);
        int jg = cBase + j;
        if (jg < posCnt) {
            if (jg != a0) num0 += e0;
            if (jg != a1) num1 += e1;
        } else { neg0 += e0; neg1 += e1; }
    }
    if (a0 < posCnt) { g_part[img][a0][blockIdx.y][0] = num0; g_part[img][a0][blockIdx.y][1] = neg0; }
    if (a1 < posCnt) { g_part[img][a1][blockIdx.y][0] = num1; g_part[img][a1][blockIdx.y][1] = neg1; }
}

// ---------------- stage 6: per-image reduction + final (fused) --------------
__global__ void k_redfinal(float* out) {
    int img = blockIdx.x;
    int tid = threadIdx.x;
    int posCnt = min(g_cnt[img][0], PCAP);
    int negCnt = min(g_cnt[img][1], NCAP);
    int nch = min(CCH, (posCnt + negCnt + CHUNK - 1) / CHUNK);
    float sum = 0.f, cnt = 0.f;
    for (int a = tid; a < posCnt; a += 256) {
        float num = 0.f, neg = 0.f;
        for (int c = 0; c < nch; ++c) {
            num += g_part[img][a][c][0];
            neg += g_part[img][a][c][1];
        }
        if (num > 0.f) { sum += log1pf(neg / num); cnt += 1.f; }  // -log(num/(num+neg))
    }
    __shared__ float ss[256], sc[256];
    ss[tid] = sum; sc[tid] = cnt;
    __syncthreads();
    for (int o = 128; o > 0; o >>= 1) {
        if (tid < o) { ss[tid] += ss[tid + o]; sc[tid] += sc[tid + o]; }
        __syncthreads();
    }
    if (tid == 0) {
        g_imgLoss[img]  = ss[0] / fmaxf(sc[0], 1.f);
        g_imgValid[img] = (posCnt >= 2 && negCnt > 0 && sc[0] > 0.f) ? 1 : 0;
        __threadfence();
        int ticket = atomicAdd(&g_done, 1);
        if (ticket == NB - 1) {                   // last image finalizes
            float v0 = g_imgValid[0] ? 1.f : 0.f;
            float v1 = g_imgValid[1] ? 1.f : 0.f;
            float s = g_imgLoss[0]*v0 + g_imgLoss[1]*v1;
            float tot = s / fmaxf(v0 + v1, 1.f);
            out[0] = (v0 + v1 > 0.f) ? tot : 0.f;
        }
    }
}

// ---------------- launch ----------------
extern "C" void kernel_launch(void* const* d_in, const int* in_sizes, int n_in,
                              void* d_out, int out_size) {
    const float* feats = (const float*)d_in[0];
    const int*   lab   = (const int*)d_in[1];
    (void)in_sizes; (void)n_in; (void)out_size;

    k_pack  <<<NROWS/8, 256>>>(lab);
    k_dilh  <<<NROWS*4/256, 256>>>();
    k_demit <<<NROWS*4/256, 256>>>();
    k_gather<<<(NB*COLCAP + 255)/256, 256>>>(feats);
    k_main  <<<dim3(PCAP/256, CCH, NB), 128>>>();
    k_redfinal<<<NB, 256>>>((float*)d_out);
}